// round 12
// baseline (speedup 1.0000x reference)
#include <cuda_runtime.h>
#include <cstdint>

#define HID   100
#define GROWS 400
#define TENC  4096
#define TDEC  4096
#define NCLS  6
#define NTH   128
#define LOG2E 1.4426950408889634f

typedef unsigned long long ull;

// precomputed input contributions, packed per-pair-thread (same as R8):
// gi = 2*j + pr:  slot0 = row (j + pr*100) [i or f], slot1 = +200 [g or o]
__device__ float g_gge[TENC * GROWS];
__device__ float g_ggd[TDEC * GROWS];

// ---- packed f32x2 / math helpers ----
__device__ __forceinline__ ull fma2(ull a, ull b, ull c) {
    ull d;
    asm("fma.rn.f32x2 %0, %1, %2, %3;" : "=l"(d) : "l"(a), "l"(b), "l"(c));
    return d;
}
__device__ __forceinline__ ull add2(ull a, ull b) {
    ull d;
    asm("add.rn.f32x2 %0, %1, %2;" : "=l"(d) : "l"(a), "l"(b));
    return d;
}
__device__ __forceinline__ float ex2f(float x) {
    float y; asm("ex2.approx.f32 %0, %1;" : "=f"(y) : "f"(x)); return y;
}
__device__ __forceinline__ float rcpf(float x) {
    float y; asm("rcp.approx.f32 %0, %1;" : "=f"(y) : "f"(x)); return y;
}
__device__ __forceinline__ float sigf(float x) {
    return rcpf(1.0f + ex2f(-LOG2E * x));
}
__device__ __forceinline__ float tanhf_fast(float x) {
    return 1.0f - 2.0f * rcpf(1.0f + ex2f((2.0f * LOG2E) * x));
}

// ---- cluster / mbarrier helpers ----
__device__ __forceinline__ unsigned smem_u32(const void* p) {
    return (unsigned)__cvta_generic_to_shared(p);
}
__device__ __forceinline__ unsigned mapa_u32(unsigned laddr, unsigned rank) {
    unsigned r;
    asm("mapa.shared::cluster.u32 %0, %1, %2;" : "=r"(r) : "r"(laddr), "r"(rank));
    return r;
}
__device__ __forceinline__ void mbar_init(unsigned a, unsigned cnt) {
    asm volatile("mbarrier.init.shared.b64 [%0], %1;" :: "r"(a), "r"(cnt) : "memory");
}
__device__ __forceinline__ void arrive_local(unsigned a) {
    asm volatile("mbarrier.arrive.release.cta.shared::cta.b64 _, [%0];"
                 :: "r"(a) : "memory");
}
__device__ __forceinline__ void arrive_remote(unsigned a) {
    asm volatile("mbarrier.arrive.release.cluster.shared::cluster.b64 _, [%0];"
                 :: "r"(a) : "memory");
}
__device__ __forceinline__ void st_remote_f32(unsigned a, float v) {
    asm volatile("st.shared::cluster.f32 [%0], %1;" :: "r"(a), "f"(v) : "memory");
}
// parity wait with cluster-scope acquire (peer DSMEM stores become visible)
#define WAITC(mb, par) do {                                                        \
    unsigned _d;                                                                   \
    asm volatile("{\n\t.reg .pred p;\n\t"                                          \
        "mbarrier.try_wait.parity.acquire.cluster.shared::cta.b64 p,[%1],%2;\n\t"  \
        "selp.b32 %0,1,0,p;\n\t}"                                                  \
        : "=r"(_d) : "r"(mb), "r"(par) : "memory");                                \
    if (!_d) {                                                                     \
        asm volatile("{\n\t.reg .pred P1;\n\t"                                     \
            "WLP_%=:\n\t"                                                          \
            "mbarrier.try_wait.parity.acquire.cluster.shared::cta.b64 P1,[%0],%1,0x989680;\n\t" \
            "@P1 bra.uni WDN_%=;\n\t"                                              \
            "bra.uni WLP_%=;\n\t"                                                  \
            "WDN_%=:\n\t}"                                                         \
            :: "r"(mb), "r"(par) : "memory");                                      \
    }                                                                              \
} while (0)
#define CLUSTER_SYNC_() do {                                                       \
    asm volatile("barrier.cluster.arrive.aligned;" ::: "memory");                  \
    asm volatile("barrier.cluster.wait.aligned;"   ::: "memory");                  \
} while (0)

// Two dots sharing each h load (R8 dotpair), 4-deep pipelined LDS.128.
__device__ __forceinline__ void dotpair(const ull (&w1)[50], const ull (&w2)[50],
                                        unsigned hb, float gx1, float gx2,
                                        float& d1, float& d2) {
    ull bxa[4], bya[4];
#pragma unroll
    for (int m = 0; m < 4; ++m)
        asm volatile("ld.shared.v2.b64 {%0,%1},[%2];"
                     : "=l"(bxa[m]), "=l"(bya[m]) : "r"(hb + 16u * m));
    ull p0, p1 = 0ull, q0, q1 = 0ull;
    asm("mov.b64 %0,{%1,%2};" : "=l"(p0) : "f"(gx1), "f"(0.0f));
    asm("mov.b64 %0,{%1,%2};" : "=l"(q0) : "f"(gx2), "f"(0.0f));
#pragma unroll
    for (int m = 0; m < 25; ++m) {
        const int sl = m & 3;
        p0 = fma2(w1[2*m],     bxa[sl], p0);
        p1 = fma2(w1[2*m + 1], bya[sl], p1);
        q0 = fma2(w2[2*m],     bxa[sl], q0);
        q1 = fma2(w2[2*m + 1], bya[sl], q1);
        if (m + 4 < 25)
            asm volatile("ld.shared.v2.b64 {%0,%1},[%2];"
                         : "=l"(bxa[sl]), "=l"(bya[sl]) : "r"(hb + 16u * (m + 4)));
    }
    ull s1 = add2(p0, p1), s2 = add2(q0, q1);
    float a, b, e, f;
    asm("mov.b64 {%0,%1},%2;" : "=f"(a), "=f"(b) : "l"(s1));
    asm("mov.b64 {%0,%1},%2;" : "=f"(e), "=f"(f) : "l"(s2));
    d1 = a + b;
    d2 = e + f;
}

// ---------------- prep kernel: gx precompute (unchanged packing) -------------
__global__ void gx_prep_kernel(const float* __restrict__ x,
                               const int*   __restrict__ y,
                               const float* __restrict__ eWih,
                               const float* __restrict__ ebih,
                               const float* __restrict__ ebhh,
                               const float* __restrict__ dWih,
                               const float* __restrict__ dbih,
                               const float* __restrict__ dbhh)
{
    int idx = blockIdx.x * blockDim.x + threadIdx.x;
    if (idx >= TENC * GROWS) return;
    int t = idx / GROWS;
    int r = idx - t * GROWS;
    int rm = r % 100, blk = r / 100;
    int thr  = 2 * rm + (blk & 1);
    int slot = blk >> 1;
    int dst = t * GROWS + thr * 2 + slot;
    g_gge[dst] = ebih[r] + ebhh[r]
               + x[3*t+0] * eWih[3*r+0]
               + x[3*t+1] * eWih[3*r+1]
               + x[3*t+2] * eWih[3*r+2];
    g_ggd[dst] = dbih[r] + dbhh[r] + (float)y[t] * dWih[r];
}

// One LSTM step for an mv thread.
__device__ __forceinline__ void lstm_step(
    const float* __restrict__ gg, int s, int Tsteps, int gi,
    const ull (&w1)[50], const ull (&w2)[50],
    unsigned hbR, float* __restrict__ hWloc, unsigned hWrem,
    float2& gx, float& c, int j, bool ev, unsigned mvmask,
    float aa2, float bb2, float kk2)
{
    int sn = s + 1; if (sn > Tsteps - 1) sn = Tsteps - 1;
    const float2 nx = __ldg(((const float2*)(gg + sn * GROWS)) + gi);
    float d1, d2;
    dotpair(w1, w2, hbR, gx.x, gx.y, d1, d2);
    const float act1 = sigf(d1);                                  // i or f
    const float act2 = fmaf(bb2, rcpf(1.0f + ex2f(kk2 * d2)), aa2); // g or o
    const float pf = __shfl_xor_sync(mvmask, act1, 1);
    const float po = __shfl_xor_sync(mvmask, act2, 1);
    if (ev) {
        c = fmaf(pf, c, act1 * act2);
        const float h = po * tanhf_fast(c);
        hWloc[j] = h;
        st_remote_f32(hWrem, h);
    }
    gx = nx;
}

__device__ __forceinline__ void logits_body(
    const float* __restrict__ hRead,
    const float* __restrict__ slw, const float* __restrict__ slb,
    float* __restrict__ out, int orow, int cls, int piece)
{
    float acc = 0.0f;
    const float* lp = slw + cls * HID + piece * 25;
    const float* hq = hRead + piece * 25;
#pragma unroll
    for (int k = 0; k < 25; ++k)
        acc = fmaf(lp[k], hq[k], acc);
    acc += __shfl_xor_sync(0xffffffffu, acc, 8);
    acc += __shfl_xor_sync(0xffffffffu, acc, 16);
    if (piece == 0 && cls < NCLS)
        out[orow * NCLS + cls] = acc + slb[cls];
}

// ---------------- persistent 2-CTA cluster kernel ----------------
__global__ void __launch_bounds__(NTH, 1) __cluster_dims__(2, 1, 1)
lstm_encdec_kernel(const float* __restrict__ eWhh,
                   const float* __restrict__ dWhh,
                   const float* __restrict__ linW,
                   const float* __restrict__ linb,
                   float* __restrict__ out)
{
    __shared__ __align__(1024) float hbuf[2][128];   // full h, both CTAs
    __shared__ float slw[8 * HID];
    __shared__ float slb[NCLS];
    __shared__ __align__(8) ull mbar[2];             // full[0], full[1]

    const int tid  = threadIdx.x;
    const unsigned rank = blockIdx.x;                // cluster spans whole grid
    const unsigned peer = rank ^ 1u;

    // roles: rank0 owns units 0-51 (104 mv thr), rank1 units 52-99 (96 mv thr)
    const int  nmv  = (rank == 0) ? 104 : 96;
    const bool mv   = tid < nmv;
    const int  j    = ((rank == 0) ? 0 : 52) + (tid >> 1);
    const int  pr   = tid & 1;
    const bool ev   = mv && (pr == 0);
    const bool lw   = (rank == 1) && (tid >= 96);    // logits warp (warp 3)
    const int  gi   = ((rank == 0) ? 0 : 104) + tid; // = 2*j + pr for mv threads
    const unsigned mvmask = (tid >= 96) ? 0xFFu : 0xFFFFFFFFu;
    const int  lane  = tid & 31;
    const int  cls   = lane & 7;
    const int  piece = lane >> 3;

    // ---- init smem ----
    hbuf[0][tid] = 0.0f; hbuf[1][tid] = 0.0f;        // tid<128 covers all
    if (rank == 1) {
        if (tid < NCLS) { out[(TDEC - 1) * NCLS + tid] = 0.0f; slb[tid] = linb[tid]; }
        for (int i = tid; i < 8 * HID; i += NTH)
            slw[i] = (i < NCLS * HID) ? linW[i] : 0.0f;
    }
    const unsigned cnt = 128u + ((rank == 0) ? 48u : 52u);  // local + peer evens
    const unsigned lmb0 = smem_u32(&mbar[0]);
    const unsigned lmb1 = lmb0 + 8u;
    if (tid == 0) { mbar_init(lmb0, cnt); mbar_init(lmb1, cnt); }
    __syncthreads();
    CLUSTER_SYNC_();                                  // peer mbars live

    // remote addresses (peer's mbars; peer's h slot for unit j)
    const unsigned rmb0 = mapa_u32(lmb0, peer);
    const unsigned rmb1 = mapa_u32(lmb1, peer);
    const unsigned lh0  = smem_u32(&hbuf[0][0]);
    const unsigned lh1  = lh0 + 512u;
    const unsigned rh0j = mapa_u32(lh0 + 4u * (unsigned)j, peer);
    const unsigned rh1j = mapa_u32(lh1 + 4u * (unsigned)j, peer);
    float* const h0 = &hbuf[0][0];
    float* const h1 = &hbuf[1][0];

    // pre-arm full[0] so the loop is uniform (h0 = 0 already stored + synced)
    if (ev) arrive_remote(rmb0);
    arrive_local(lmb0);

    // act2 constants: pr=0 -> tanh (g), pr=1 -> sigmoid (o)
    const float aa2 = (pr == 0) ? 1.0f : 0.0f;
    const float bb2 = (pr == 0) ? -2.0f : 1.0f;
    const float kk2 = (pr == 0) ? (2.0f * LOG2E) : (-LOG2E);
    const int r1 = j + pr * 100;
    const int r2 = r1 + 200;

    // ---- encoder weights ----
    ull w1[50], w2[50];
    if (mv) {
        const ull* p1 = (const ull*)(eWhh + r1 * HID);
        const ull* p2 = (const ull*)(eWhh + r2 * HID);
#pragma unroll
        for (int k = 0; k < 50; ++k) { w1[k] = p1[k]; w2[k] = p2[k]; }
    }
    float c = 0.0f;
    float2 gx = make_float2(0.0f, 0.0f);
    if (mv) gx = __ldg(((const float2*)g_gge) + gi);

    unsigned ph0 = 0, ph1 = 0;

    // ================= encoder: 4096 steps (2048 iters) =================
#pragma unroll 1
    for (int it = 0; it < TENC / 2; ++it) {
        WAITC(lmb0, ph0); ph0 ^= 1u;                 // buf0 ready
        if (mv) lstm_step(g_gge, 2*it, TENC, gi, w1, w2, lh0, h1, rh1j,
                          gx, c, j, ev, mvmask, aa2, bb2, kk2);
        if (ev) arrive_remote(rmb1);
        arrive_local(lmb1);

        WAITC(lmb1, ph1); ph1 ^= 1u;                 // buf1 ready
        if (mv) lstm_step(g_gge, 2*it + 1, TENC, gi, w1, w2, lh1, h0, rh0j,
                          gx, c, j, ev, mvmask, aa2, bb2, kk2);
        if (ev) arrive_remote(rmb0);
        arrive_local(lmb0);
    }
    // h_enc in buf0; protocol state: next wait is (lmb0, ph0)

    // ---- decoder weights (registers only) ----
    if (mv) {
        const ull* p1 = (const ull*)(dWhh + r1 * HID);
        const ull* p2 = (const ull*)(dWhh + r2 * HID);
#pragma unroll
        for (int k = 0; k < 50; ++k) { w1[k] = p1[k]; w2[k] = p2[k]; }
        gx = __ldg(((const float2*)g_ggd) + gi);
    }

    // ================= decoder: 4095 LSTM steps =================
    // d = 2it (reads buf0), d = 2it+1 (reads buf1); logits lag one step.
#pragma unroll 1
    for (int it = 0; it < (TDEC - 2) / 2; ++it) {    // d = 0..4093
        WAITC(lmb0, ph0); ph0 ^= 1u;
        if (mv) {
            lstm_step(g_ggd, 2*it, TDEC - 1, gi, w1, w2, lh0, h1, rh1j,
                      gx, c, j, ev, mvmask, aa2, bb2, kk2);
        } else if (lw && it > 0) {
            logits_body(h0, slw, slb, out, 2*it - 1, cls, piece);
        }
        if (ev) arrive_remote(rmb1);
        arrive_local(lmb1);

        WAITC(lmb1, ph1); ph1 ^= 1u;
        if (mv) {
            lstm_step(g_ggd, 2*it + 1, TDEC - 1, gi, w1, w2, lh1, h0, rh0j,
                      gx, c, j, ev, mvmask, aa2, bb2, kk2);
        } else if (lw) {
            logits_body(h1, slw, slb, out, 2*it, cls, piece);
        }
        if (ev) arrive_remote(rmb0);
        arrive_local(lmb0);
    }
    // final LSTM step d = 4094 (reads buf0 -> writes buf1); logits row 4093
    WAITC(lmb0, ph0); ph0 ^= 1u;
    if (mv) {
        lstm_step(g_ggd, TDEC - 2, TDEC - 1, gi, w1, w2, lh0, h1, rh1j,
                  gx, c, j, ev, mvmask, aa2, bb2, kk2);
    } else if (lw) {
        logits_body(h0, slw, slb, out, TDEC - 3, cls, piece);
    }
    if (ev) arrive_remote(rmb1);
    arrive_local(lmb1);

    // logits row 4094 from buf1 (row 4095 stays zero)
    WAITC(lmb1, ph1);
    if (lw) logits_body(h1, slw, slb, out, TDEC - 2, cls, piece);

    CLUSTER_SYNC_();                                  // no early CTA exit
}

extern "C" void kernel_launch(void* const* d_in, const int* in_sizes, int n_in,
                              void* d_out, int out_size) {
    const float* x     = (const float*)d_in[0];
    const int*   y     = (const int*)  d_in[1];
    const float* eWih  = (const float*)d_in[2];
    const float* eWhh  = (const float*)d_in[3];
    const float* ebih  = (const float*)d_in[4];
    const float* ebhh  = (const float*)d_in[5];
    const float* dWih  = (const float*)d_in[6];
    const float* dWhh  = (const float*)d_in[7];
    const float* dbih  = (const float*)d_in[8];
    const float* dbhh  = (const float*)d_in[9];
    const float* linW  = (const float*)d_in[10];
    const float* linb  = (const float*)d_in[11];
    float* out = (float*)d_out;

    const int n = TENC * GROWS;
    gx_prep_kernel<<<(n + 255) / 256, 256>>>(x, y, eWih, ebih, ebhh,
                                             dWih, dbih, dbhh);
    lstm_encdec_kernel<<<2, NTH>>>(eWhh, dWhh, linW, linb, out);
}

// round 13
// speedup vs baseline: 1.2328x; 1.2328x over previous
#include <cuda_runtime.h>
#include <cstdint>

#define HID   100
#define GROWS 400
#define GXS   512          // gx slots per step (400 used)
#define TENC  4096
#define TDEC  4096
#define NCLS  6
#define NTH   256
#define LOG2E 1.4426950408889634f

typedef unsigned long long ull;

// gx layout per step (offset within GXS block):
//  tids 0-127  (pair warps, units 0-63):  2*tid + {0,1}        -> 0..255
//  tids 128-223 (single warps, units 64-87): 256 + (tid-128)   -> 256..351
//  w7 full rows (units 88-95):            352 + lane           -> 352..383
//  w7 half rows (units 96-99):            384 + (lane>>1)      -> 384..399
__device__ float g_gge[TENC * GXS];
__device__ float g_ggd[TDEC * GXS];

// ---- packed f32x2 / math helpers ----
__device__ __forceinline__ ull fma2(ull a, ull b, ull c) {
    ull d;
    asm("fma.rn.f32x2 %0, %1, %2, %3;" : "=l"(d) : "l"(a), "l"(b), "l"(c));
    return d;
}
__device__ __forceinline__ ull add2(ull a, ull b) {
    ull d;
    asm("add.rn.f32x2 %0, %1, %2;" : "=l"(d) : "l"(a), "l"(b));
    return d;
}
__device__ __forceinline__ float ex2f(float x) {
    float y; asm("ex2.approx.f32 %0, %1;" : "=f"(y) : "f"(x)); return y;
}
__device__ __forceinline__ float rcpf(float x) {
    float y; asm("rcp.approx.f32 %0, %1;" : "=f"(y) : "f"(x)); return y;
}
__device__ __forceinline__ float sigf(float x) {
    return rcpf(1.0f + ex2f(-LOG2E * x));
}
__device__ __forceinline__ float tanhf_fast(float x) {
    return 1.0f - 2.0f * rcpf(1.0f + ex2f((2.0f * LOG2E) * x));
}
__device__ __forceinline__ float hsum2(ull s) {
    float lo, hi;
    asm("mov.b64 {%0,%1},%2;" : "=f"(lo), "=f"(hi) : "l"(s));
    return lo + hi;
}
// gate activation consts: gt==2 -> tanh, else sigmoid
__device__ __forceinline__ void gconst(int gt, float& aa, float& bb, float& kk) {
    const bool tg = (gt == 2);
    aa = tg ? 1.0f : 0.0f;
    bb = tg ? -2.0f : 1.0f;
    kk = tg ? (2.0f * LOG2E) : (-LOG2E);
}
__device__ __forceinline__ float act_gate(float x, float aa, float bb, float kk) {
    return fmaf(bb, rcpf(1.0f + ex2f(kk * x)), aa);
}

// ---- dots ----
// R8 dotpair: two full rows sharing each h load; gx in accumulator init.
__device__ __forceinline__ void dotpair(const ull (&w1)[50], const ull (&w2)[50],
                                        unsigned hb, float gx1, float gx2,
                                        float& d1, float& d2) {
    ull bxa[4], bya[4];
#pragma unroll
    for (int m = 0; m < 4; ++m)
        asm volatile("ld.shared.v2.b64 {%0,%1},[%2];"
                     : "=l"(bxa[m]), "=l"(bya[m]) : "r"(hb + 16u * m));
    ull p0, p1 = 0ull, q0, q1 = 0ull;
    asm("mov.b64 %0,{%1,%2};" : "=l"(p0) : "f"(gx1), "f"(0.0f));
    asm("mov.b64 %0,{%1,%2};" : "=l"(q0) : "f"(gx2), "f"(0.0f));
#pragma unroll
    for (int m = 0; m < 25; ++m) {
        const int sl = m & 3;
        p0 = fma2(w1[2*m],     bxa[sl], p0);
        p1 = fma2(w1[2*m + 1], bya[sl], p1);
        q0 = fma2(w2[2*m],     bxa[sl], q0);
        q1 = fma2(w2[2*m + 1], bya[sl], q1);
        if (m + 4 < 25)
            asm volatile("ld.shared.v2.b64 {%0,%1},[%2];"
                         : "=l"(bxa[sl]), "=l"(bya[sl]) : "r"(hb + 16u * (m + 4)));
    }
    d1 = hsum2(add2(p0, p1));
    d2 = hsum2(add2(q0, q1));
}

// single full row (50 FFMA2), 4-deep pipelined
__device__ __forceinline__ float dot_single(const ull (&w)[50], unsigned hb) {
    ull bx[4], by[4];
#pragma unroll
    for (int m = 0; m < 4; ++m)
        asm volatile("ld.shared.v2.b64 {%0,%1},[%2];"
                     : "=l"(bx[m]), "=l"(by[m]) : "r"(hb + 16u * m));
    ull a0 = 0ull, a1 = 0ull;
#pragma unroll
    for (int m = 0; m < 25; ++m) {
        const int sl = m & 3;
        a0 = fma2(w[2*m],     bx[sl], a0);
        a1 = fma2(w[2*m + 1], by[sl], a1);
        if (m + 4 < 25)
            asm volatile("ld.shared.v2.b64 {%0,%1},[%2];"
                         : "=l"(bx[sl]), "=l"(by[sl]) : "r"(hb + 16u * (m + 4)));
    }
    return hsum2(add2(a0, a1));
}

// w7: one full (possibly K-rotated) row + one half-row on the same loads (76 FFMA2)
__device__ __forceinline__ void dot_w7(const ull (&w1)[50], const ull (&w2)[50],
                                       unsigned base, float& sF, float& sH) {
    ull bx[4], by[4];
#pragma unroll
    for (int m = 0; m < 4; ++m)
        asm volatile("ld.shared.v2.b64 {%0,%1},[%2];"
                     : "=l"(bx[m]), "=l"(by[m]) : "r"(base + 16u * m));
    ull a0 = 0ull, a1 = 0ull, b0 = 0ull, b1 = 0ull;
#pragma unroll
    for (int m = 0; m < 25; ++m) {
        const int sl = m & 3;
        const ull hx = bx[sl], hy = by[sl];
        if (m + 4 < 25)
            asm volatile("ld.shared.v2.b64 {%0,%1},[%2];"
                         : "=l"(bx[sl]), "=l"(by[sl]) : "r"(base + 16u * (m + 4)));
        a0 = fma2(w1[2*m],     hx, a0);
        a1 = fma2(w1[2*m + 1], hy, a1);
        if (m < 13) {
            b0 = fma2(w2[2*m],     hx, b0);
            b1 = fma2(w2[2*m + 1], hy, b1);
        }
    }
    sF = hsum2(add2(a0, a1));
    sH = hsum2(add2(b0, b1));
}

// ---------------- prep kernel ----------------
__global__ void gx_prep_kernel(const float* __restrict__ x,
                               const int*   __restrict__ y,
                               const float* __restrict__ eWih,
                               const float* __restrict__ ebih,
                               const float* __restrict__ ebhh,
                               const float* __restrict__ dWih,
                               const float* __restrict__ dbih,
                               const float* __restrict__ dbhh)
{
    int idx = blockIdx.x * blockDim.x + threadIdx.x;
    if (idx >= TENC * GROWS) return;
    int t = idx / GROWS;
    int r = idx - t * GROWS;
    int u = r % 100, gt = r / 100;          // gt: 0=i,1=f,2=g,3=o
    int off;
    if (u < 64)       off = 4*u + 2*(gt & 1) + (gt >> 1);
    else if (u < 88)  off = 256 + (u - 64) * 4 + gt;
    else if (u < 96)  off = 352 + (u - 88) * 4 + gt;
    else              off = 384 + (u - 96) * 4 + gt;
    int dst = t * GXS + off;
    g_gge[dst] = ebih[r] + ebhh[r]
               + x[3*t+0] * eWih[3*r+0]
               + x[3*t+1] * eWih[3*r+1]
               + x[3*t+2] * eWih[3*r+2];
    g_ggd[dst] = dbih[r] + dbhh[r] + (float)y[t] * dWih[r];
}

// ---- per-class weight loading ----
__device__ __forceinline__ void load_weights(const float* __restrict__ Whh,
                                             int tid, ull (&w1)[50], ull (&w2)[50]) {
    const int wid = tid >> 5, lane = tid & 31;
    if (wid < 4) {
        const int j = tid >> 1, pr = tid & 1;
        const ull* p1 = (const ull*)(Whh + (j + pr * 100) * HID);
        const ull* p2 = (const ull*)(Whh + (j + pr * 100 + 200) * HID);
#pragma unroll
        for (int k = 0; k < 50; ++k) { w1[k] = p1[k]; w2[k] = p2[k]; }
    } else if (wid < 7) {
        const int li = tid - 128;
        const ull* p = (const ull*)(Whh + ((64 + (li >> 2)) + (li & 3) * 100) * HID);
#pragma unroll
        for (int k = 0; k < 50; ++k) w1[k] = p[k];
    } else {
        const int rF = (88 + (lane >> 2)) + (lane & 3) * 100;
        const int m  = lane >> 1;
        const int rH = (96 + (m >> 2)) + (m & 3) * 100;
        const float* pF = Whh + rF * HID;
        const float* pH = Whh + rH * HID;
        if (lane & 1) {   // rotated: reads h cols [52..99,0..51] via dup region
            const ull* a = (const ull*)(pF + 52);
#pragma unroll
            for (int k = 0; k < 24; ++k) w1[k] = a[k];
            const ull* b = (const ull*)pF;
#pragma unroll
            for (int k = 0; k < 26; ++k) w1[24 + k] = b[k];
            const ull* hh = (const ull*)(pH + 52);
#pragma unroll
            for (int k = 0; k < 24; ++k) w2[k] = hh[k];
            w2[24] = 0ull; w2[25] = 0ull;
        } else {
            const ull* a = (const ull*)pF;
#pragma unroll
            for (int k = 0; k < 50; ++k) w1[k] = a[k];
            const ull* hh = (const ull*)pH;
#pragma unroll
            for (int k = 0; k < 26; ++k) w2[k] = hh[k];
        }
    }
}

__device__ __forceinline__ void logits_body(
    const float* __restrict__ hRead,
    const float* __restrict__ slw, const float* __restrict__ slb,
    float* __restrict__ out, int orow, int lane)
{
    const int cls = lane & 7, piece = lane >> 3;
    float acc = 0.0f;
    const float* lp = slw + cls * HID + piece * 25;   // cls 6,7 hit zero pad
    const float* hq = hRead + piece * 25;
#pragma unroll
    for (int k = 0; k < 25; ++k)
        acc = fmaf(lp[k], hq[k], acc);
    acc += __shfl_xor_sync(0xffffffffu, acc, 8);
    acc += __shfl_xor_sync(0xffffffffu, acc, 16);
    if (piece == 0 && cls < NCLS)
        out[orow * NCLS + cls] = acc + slb[cls];
}

// one step, all warp classes
template<bool DEC>
__device__ __forceinline__ void do_step(
    int s, int Twork, const float* __restrict__ gg,
    const ull (&w1)[50], const ull (&w2)[50],
    unsigned hbR, float* __restrict__ hW, const float* __restrict__ hRptr,
    float2& gx2, float& gxH, float& c1, float& c2,
    int tid, float aa1, float bb1, float kk1,
    float aa2h, float bb2h, float kk2h,
    const float* __restrict__ slw, const float* __restrict__ slb,
    float* __restrict__ out)
{
    const int wid = tid >> 5, lane = tid & 31;
    int sn = s + 1; if (sn > Twork - 1) sn = Twork - 1;
    const float* gbase = gg + sn * GXS;

    if (wid < 4) {
        // ---- pair warps: units 0-63 ----
        const float2 nx = __ldg(((const float2*)gbase) + tid);
        float d1, d2;
        dotpair(w1, w2, hbR, gx2.x, gx2.y, d1, d2);
        const float act1 = sigf(d1);                          // i or f
        const float act2 = act_gate(d2, aa1, bb1, kk1);       // g (even) / o (odd)
        const float pf = __shfl_xor_sync(0xffffffffu, act1, 1);
        const float po = __shfl_xor_sync(0xffffffffu, act2, 1);
        if (!(tid & 1)) {
            const int j = tid >> 1;
            c1 = fmaf(pf, c1, act1 * act2);
            const float h = po * tanhf_fast(c1);
            hW[j] = h;
            if (j < 52) hW[100 + j] = h;                      // dup for w7 rotation
        }
        gx2 = nx;
    } else if (wid < 7) {
        // ---- single-row warps: units 64-87 (4 lanes per unit) ----
        const int li = tid - 128;
        const float nx = __ldg(gbase + 256 + li);
        const float sd = dot_single(w1, hbR) + gx2.x;
        const float act = act_gate(sd, aa1, bb1, kk1);
        const int lb = lane & ~3;
        const float iv = __shfl_sync(0xffffffffu, act, lb);
        const float fv = __shfl_sync(0xffffffffu, act, lb + 1);
        const float gv = __shfl_sync(0xffffffffu, act, lb + 2);
        const float ov = __shfl_sync(0xffffffffu, act, lb + 3);
        c1 = fmaf(fv, c1, iv * gv);
        const float h = ov * tanhf_fast(c1);
        if ((lane & 3) == 0) hW[64 + (li >> 2)] = h;
        gx2.x = nx;
        if (DEC && wid == 6 && s >= 1)
            logits_body(hRptr, slw, slb, out, s - 1, lane);
    } else {
        // ---- w7: units 88-95 (full rows) + 96-99 (K-split pairs) ----
        const float nxF = __ldg(gbase + 352 + lane);
        const float nxH = __ldg(gbase + 384 + (lane >> 1));
        float sF, sHp;
        dot_w7(w1, w2, hbR + 208u * (unsigned)(lane & 1), sF, sHp);
        sF += gx2.x;
        float sH = sHp + __shfl_xor_sync(0xffffffffu, sHp, 1);
        if (!(lane & 1)) sH += gxH;                            // even total is valid
        const float actF = act_gate(sF, aa1, bb1, kk1);
        const float actH = act_gate(sH, aa2h, bb2h, kk2h);
        const int bA = lane & ~3;
        const float iA = __shfl_sync(0xffffffffu, actF, bA);
        const float fA = __shfl_sync(0xffffffffu, actF, bA + 1);
        const float gA = __shfl_sync(0xffffffffu, actF, bA + 2);
        const float oA = __shfl_sync(0xffffffffu, actF, bA + 3);
        c1 = fmaf(fA, c1, iA * gA);
        const float hA = oA * tanhf_fast(c1);
        const int bB = lane & ~7;                              // even-lane sources
        const float iB = __shfl_sync(0xffffffffu, actH, bB);
        const float fB = __shfl_sync(0xffffffffu, actH, bB + 2);
        const float gB = __shfl_sync(0xffffffffu, actH, bB + 4);
        const float oB = __shfl_sync(0xffffffffu, actH, bB + 6);
        c2 = fmaf(fB, c2, iB * gB);
        const float hB = oB * tanhf_fast(c2);
        if ((lane & 3) == 0) hW[88 + (lane >> 2)] = hA;
        if ((lane & 7) == 0) hW[96 + (lane >> 3)] = hB;
        gx2.x = nxF; gxH = nxH;
    }
}

// ---------------- persistent recurrence kernel ----------------
__global__ void __launch_bounds__(NTH, 1)
lstm_encdec_kernel(const float* __restrict__ eWhh,
                   const float* __restrict__ dWhh,
                   const float* __restrict__ linW,
                   const float* __restrict__ linb,
                   float* __restrict__ out)
{
    __shared__ __align__(2048) float hbuf[2][256];   // cols 0-99 h, 100-151 dup h[0:51]
    __shared__ float slw[8 * HID];
    __shared__ float slb[NCLS];

    const int tid = threadIdx.x;
    const int wid = tid >> 5, lane = tid & 31;

    hbuf[0][tid] = 0.0f; hbuf[1][tid] = 0.0f;        // 256 each, all cols
    if (tid < NCLS) { out[(TDEC - 1) * NCLS + tid] = 0.0f; slb[tid] = linb[tid]; }
    for (int i = tid; i < 8 * HID; i += NTH)
        slw[i] = (i < NCLS * HID) ? linW[i] : 0.0f;

    // hoisted activation constants
    float aa1, bb1, kk1, aa2h = 0.f, bb2h = 1.f, kk2h = -LOG2E;
    if (wid < 4)       gconst((tid & 1) ? 3 : 2, aa1, bb1, kk1);
    else if (wid < 7)  gconst(lane & 3, aa1, bb1, kk1);
    else { gconst(lane & 3, aa1, bb1, kk1); gconst((lane >> 1) & 3, aa2h, bb2h, kk2h); }

    ull w1[50], w2[50];
    load_weights(eWhh, tid, w1, w2);
    float c1 = 0.0f, c2 = 0.0f;
    __syncthreads();

    const unsigned hb0 = (unsigned)__cvta_generic_to_shared(&hbuf[0][0]);
    const unsigned hb1 = hb0 + 1024u;
    float* const h0 = &hbuf[0][0];
    float* const h1 = &hbuf[1][0];

    // initial gx (step 0)
    float2 gx2 = make_float2(0.f, 0.f);
    float  gxH = 0.f;
    if (wid < 4)      gx2 = __ldg(((const float2*)g_gge) + tid);
    else if (wid < 7) gx2.x = __ldg(g_gge + 256 + (tid - 128));
    else { gx2.x = __ldg(g_gge + 352 + lane); gxH = __ldg(g_gge + 384 + (lane >> 1)); }

    // ================= encoder: 4096 steps =================
#pragma unroll 1
    for (int it = 0; it < TENC / 2; ++it) {
        do_step<false>(2*it,     TENC, g_gge, w1, w2, hb0, h1, h0, gx2, gxH, c1, c2,
                       tid, aa1, bb1, kk1, aa2h, bb2h, kk2h, slw, slb, out);
        __syncthreads();
        do_step<false>(2*it + 1, TENC, g_gge, w1, w2, hb1, h0, h1, gx2, gxH, c1, c2,
                       tid, aa1, bb1, kk1, aa2h, bb2h, kk2h, slw, slb, out);
        __syncthreads();
    }
    // h_enc in hbuf[0]

    // ---- decoder weights + first gx (registers only) ----
    load_weights(dWhh, tid, w1, w2);
    if (wid < 4)      gx2 = __ldg(((const float2*)g_ggd) + tid);
    else if (wid < 7) gx2.x = __ldg(g_ggd + 256 + (tid - 128));
    else { gx2.x = __ldg(g_ggd + 352 + lane); gxH = __ldg(g_ggd + 384 + (lane >> 1)); }

    // ================= decoder: 4095 work steps =================
    const int TW = TDEC - 1;   // 4095
#pragma unroll 1
    for (int it = 0; it < (TW - 1) / 2; ++it) {      // steps 0..4093
        do_step<true>(2*it,     TW, g_ggd, w1, w2, hb0, h1, h0, gx2, gxH, c1, c2,
                      tid, aa1, bb1, kk1, aa2h, bb2h, kk2h, slw, slb, out);
        __syncthreads();
        do_step<true>(2*it + 1, TW, g_ggd, w1, w2, hb1, h0, h1, gx2, gxH, c1, c2,
                      tid, aa1, bb1, kk1, aa2h, bb2h, kk2h, slw, slb, out);
        __syncthreads();
    }
    // step 4094: reads buf0, writes buf1; logits row 4093 from buf0
    do_step<true>(TW - 1, TW, g_ggd, w1, w2, hb0, h1, h0, gx2, gxH, c1, c2,
                  tid, aa1, bb1, kk1, aa2h, bb2h, kk2h, slw, slb, out);
    __syncthreads();
    // logits row 4094 from buf1 (row 4095 stays zero)
    if (wid == 6) logits_body(h1, slw, slb, out, TDEC - 2, lane);
}

extern "C" void kernel_launch(void* const* d_in, const int* in_sizes, int n_in,
                              void* d_out, int out_size) {
    const float* x     = (const float*)d_in[0];
    const int*   y     = (const int*)  d_in[1];
    const float* eWih  = (const float*)d_in[2];
    const float* eWhh  = (const float*)d_in[3];
    const float* ebih  = (const float*)d_in[4];
    const float* ebhh  = (const float*)d_in[5];
    const float* dWih  = (const float*)d_in[6];
    const float* dWhh  = (const float*)d_in[7];
    const float* dbih  = (const float*)d_in[8];
    const float* dbhh  = (const float*)d_in[9];
    const float* linW  = (const float*)d_in[10];
    const float* linb  = (const float*)d_in[11];
    float* out = (float*)d_out;

    const int n = TENC * GROWS;
    gx_prep_kernel<<<(n + 255) / 256, 256>>>(x, y, eWih, ebih, ebhh,
                                             dWih, dbih, dbhh);
    lstm_encdec_kernel<<<1, NTH>>>(eWhh, dWhh, linW, linb, out);
}